// round 16
// baseline (speedup 1.0000x reference)
#include <cuda_runtime.h>

#define BATCH 64
#define IN_F  512
#define OUT_F 512
#define NB    8
#define KDIM  9            // slot 0 = silu (pairs with w), 1..8 = T_k (pair with c*w)

#define O_TILE 64
#define IC     8           // i-range per CTA (split-K)
#define NSPLIT (IN_F / IC) // 64
#define N_OT   (OUT_F / O_TILE) // 8

// Scratch (static device globals — no allocation). cnt_g zero-init; reset after use.
__device__ float A_g[IN_F * KDIM * BATCH];     // [i][k][b], 1.18 MB (L2-resident)
__device__ float P_g[NSPLIT * BATCH * OUT_F];  // split-K partials, 8 MB (L2-resident)
__device__ int   cnt_g[N_OT];

// ---------------------------------------------------------------------------
// Kernel 1: basis + silu precompute, 1x work, coalesced loads AND stores.
// Grid 128 CTAs x 256 thr; CTA covers 4 i's x 64 b.
// ---------------------------------------------------------------------------
__global__ __launch_bounds__(256) void prep_kernel(const float* __restrict__ x) {
    __shared__ float sx[BATCH][4];          // x sub-block [b][il]
    __shared__ float sT[4][KDIM][BATCH];    // staged A tile, 9 KB

    const int t  = threadIdx.x;
    const int i0 = blockIdx.x * 4;

    // Phase 1: 64 threads pull one float4 row-slice each (64 in flight).
    if (t < BATCH) {
        const float4 v = *(const float4*)&x[t * IN_F + i0];
        sx[t][0] = v.x; sx[t][1] = v.y; sx[t][2] = v.z; sx[t][3] = v.w;
    }
    __syncthreads();

    // Phase 2: one (il, b) point per thread; stores to smem (b lane-fast, conflict-free).
    {
        const int il = t >> 6;     // 0..3
        const int b  = t & 63;
        const float xv = sx[b][il];
        float tt = tanhf(xv);
        const float lim = 1.0f - 1e-6f;
        tt = fminf(fmaxf(tt, -lim), lim);
        // silu(x) = x * 0.5 * (1 + tanh(x/2))  (exact identity)
        const float sil = xv * 0.5f * (1.0f + tanhf(0.5f * xv));
        sT[il][0][b] = sil;
        float tkm1 = 1.0f, tk = tt;
        sT[il][1][b] = tt;
#pragma unroll
        for (int k = 2; k <= NB; ++k) {
            const float tn = 2.0f * tt * tk - tkm1;
            sT[il][k][b] = tn;
            tkm1 = tk; tk = tn;
        }
    }
    __syncthreads();

    // Phase 3: fully-coalesced float4 writeback (sT linear order == A_g block order).
    {
        const float4* src = (const float4*)sT;
        float4* dst = (float4*)(A_g + i0 * (KDIM * BATCH));
        const int nf4 = 4 * KDIM * BATCH / 4;  // 576
#pragma unroll
        for (int idx = t; idx < nf4; idx += 256) dst[idx] = src[idx];
    }
}

// ---------------------------------------------------------------------------
// Packed f32x2 helpers (FFMA2 path — not reachable from plain C++)
// ---------------------------------------------------------------------------
__device__ __forceinline__ unsigned long long rep2(float v) {
    unsigned long long r;
    asm("mov.b64 %0, {%1, %1};" : "=l"(r) : "f"(v));
    return r;
}
__device__ __forceinline__ void fma2(unsigned long long& d,
                                     unsigned long long a,
                                     unsigned long long b) {
    asm("fma.rn.f32x2 %0, %1, %2, %0;" : "+l"(d) : "l"(a), "l"(b));
}
__device__ __forceinline__ float2 unpk(unsigned long long v) {
    float2 f;
    asm("mov.b64 {%0, %1}, %2;" : "=f"(f.x), "=f"(f.y) : "l"(v));
    return f;
}

// ---------------------------------------------------------------------------
// Kernel 2: GEMM + last-block split-K reduction. Grid (8, 64), 256 thr.
// Single front-loaded load phase (MLP~11/thread), one sync, barrier-free K-loop.
// ---------------------------------------------------------------------------
__global__ __launch_bounds__(256) void gemm_kernel(const float* __restrict__ w,
                                                   const float* __restrict__ c,
                                                   float* __restrict__ out) {
    __shared__ float sA[IC][KDIM][BATCH];    // 18 KB
    __shared__ float sCW[IC][KDIM][O_TILE];  // 18 KB
    __shared__ int sLast;

    const int tid  = threadIdx.x;
    const int o0   = blockIdx.x * O_TILE;
    const int i0   = blockIdx.y * IC;
    const int t_og = tid & 31;   // o_local = 2*t_og
    const int t_bg = tid >> 5;   // warp id: batch base = 8*t_bg (broadcast LDS)

    // ---- Load phase: issue everything, then one sync ----
    // A tile: 8*9*64 = 4608 floats = 1152 float4; 4-5 per thread (L2 hits).
    float4 a_reg[5];
    const float4* srcA = (const float4*)(A_g + i0 * (KDIM * BATCH));
#pragma unroll
    for (int q = 0; q < 5; ++q) {
        const int idx = tid + 256 * q;
        if (idx < IC * KDIM * BATCH / 4) a_reg[q] = srcA[idx];
    }
    // c/w: two (ii, ol) pairs per thread: (tid>>6, tid&63) and (+4, same ol).
    const int ii_a = tid >> 6;          // 0..3
    const int ii_b = ii_a + 4;          // 4..7
    const int ol   = tid & 63;
    const int io_a = (i0 + ii_a) * OUT_F + (o0 + ol);
    const int io_b = (i0 + ii_b) * OUT_F + (o0 + ol);
    const float4* cpa = (const float4*)(c + (size_t)io_a * NB);
    const float4* cpb = (const float4*)(c + (size_t)io_b * NB);
    const float4 c0a = cpa[0]; const float4 c1a = cpa[1];
    const float4 c0b = cpb[0]; const float4 c1b = cpb[1];
    const float  wa  = w[io_a];
    const float  wb  = w[io_b];

    // Stores to smem.
    {
        float4* dA = (float4*)sA;
#pragma unroll
        for (int q = 0; q < 5; ++q) {
            const int idx = tid + 256 * q;
            if (idx < IC * KDIM * BATCH / 4) dA[idx] = a_reg[q];
        }
        sCW[ii_a][0][ol] = wa;
        sCW[ii_a][1][ol] = c0a.x * wa;
        sCW[ii_a][2][ol] = c0a.y * wa;
        sCW[ii_a][3][ol] = c0a.z * wa;
        sCW[ii_a][4][ol] = c0a.w * wa;
        sCW[ii_a][5][ol] = c1a.x * wa;
        sCW[ii_a][6][ol] = c1a.y * wa;
        sCW[ii_a][7][ol] = c1a.z * wa;
        sCW[ii_a][8][ol] = c1a.w * wa;
        sCW[ii_b][0][ol] = wb;
        sCW[ii_b][1][ol] = c0b.x * wb;
        sCW[ii_b][2][ol] = c0b.y * wb;
        sCW[ii_b][3][ol] = c0b.z * wb;
        sCW[ii_b][4][ol] = c0b.w * wb;
        sCW[ii_b][5][ol] = c1b.x * wb;
        sCW[ii_b][6][ol] = c1b.y * wb;
        sCW[ii_b][7][ol] = c1b.z * wb;
        sCW[ii_b][8][ol] = c1b.w * wb;
    }
    __syncthreads();

    // ---- Compute: 72 barrier-free iterations ----
    unsigned long long acc[2][4];
#pragma unroll
    for (int oo = 0; oo < 2; ++oo)
#pragma unroll
        for (int bp = 0; bp < 4; ++bp) acc[oo][bp] = 0ull;

#pragma unroll
    for (int ii = 0; ii < IC; ++ii) {
#pragma unroll
        for (int k = 0; k < KDIM; ++k) {
            // A: warp-uniform -> broadcast, conflict-free, 16B-aligned.
            ulonglong2 A0 = *(const ulonglong2*)&sA[ii][k][8 * t_bg];
            ulonglong2 A1 = *(const ulonglong2*)&sA[ii][k][8 * t_bg + 4];
            float2 cw = *(const float2*)&sCW[ii][k][2 * t_og];
            unsigned long long cx = rep2(cw.x);
            unsigned long long cy = rep2(cw.y);
            fma2(acc[0][0], A0.x, cx);
            fma2(acc[1][0], A0.x, cy);
            fma2(acc[0][1], A0.y, cx);
            fma2(acc[1][1], A0.y, cy);
            fma2(acc[0][2], A1.x, cx);
            fma2(acc[1][2], A1.x, cy);
            fma2(acc[0][3], A1.y, cx);
            fma2(acc[1][3], A1.y, cy);
        }
    }

    // ---- Store partials; last CTA per o-tile reduces (deterministic order) ----
    {
        float* P = P_g + blockIdx.y * (BATCH * OUT_F);
#pragma unroll
        for (int oo = 0; oo < 2; ++oo)
#pragma unroll
            for (int bp = 0; bp < 4; ++bp) {
                float2 v = unpk(acc[oo][bp]);
                const int o = o0 + 2 * t_og + oo;
                const int b = 8 * t_bg + 2 * bp;
                P[b * OUT_F + o]       = v.x;
                P[(b + 1) * OUT_F + o] = v.y;
            }
    }
    __threadfence();  // release partials
    if (tid == 0) {
        const int old = atomicAdd(&cnt_g[blockIdx.x], 1);
        sLast = (old == NSPLIT - 1);
    }
    __syncthreads();

    if (sLast) {
        __threadfence();  // acquire partials
        // 64 b x 16 float4 of o = 1024 float4 outputs; 4 per thread.
#pragma unroll
        for (int q = 0; q < 4; ++q) {
            const int idx = tid + 256 * q;
            const int b   = idx >> 4;
            const int of4 = (idx & 15) * 4;
            float4 s = make_float4(0.f, 0.f, 0.f, 0.f);
#pragma unroll 8
            for (int p = 0; p < NSPLIT; ++p) {
                const float4 v = *(const float4*)&P_g[(size_t)(p * BATCH + b) * OUT_F + o0 + of4];
                s.x += v.x; s.y += v.y; s.z += v.z; s.w += v.w;
            }
            *(float4*)&out[b * OUT_F + o0 + of4] = s;
        }
        if (tid == 0) cnt_g[blockIdx.x] = 0;  // reset for next graph replay
    }
}

// ---------------------------------------------------------------------------
extern "C" void kernel_launch(void* const* d_in, const int* in_sizes, int n_in,
                              void* d_out, int out_size) {
    const float* x = (const float*)d_in[0];  // (64, 512)
    const float* w = (const float*)d_in[1];  // (512, 512)
    const float* c = (const float*)d_in[2];  // (512, 512, 8)
    float* out = (float*)d_out;              // (64, 512)

    prep_kernel<<<IN_F / 4, 256>>>(x);
    gemm_kernel<<<dim3(N_OT, NSPLIT), 256>>>(w, c, out);
}